// round 14
// baseline (speedup 1.0000x reference)
#include <cuda_runtime.h>
#include <math.h>

// Problem dims (fixed by the dataset)
#define B 1024
#define S 64
#define E 256
#define H 512
#define V 128
#define C 32

#define BT    8
#define HPAIR 256          // h-pairs
#define THR   1024

// buckets: NB4 CTAs (longest rows, 608..1023), NB8 CTAs (rows 0..607 desc)
#define N_CTA4  104
#define N_CTA8  76
#define RNN_GRID (N_CTA4 + N_CTA8)   // 180

// dynamic smem (worst case = NB8 path): 16384 (state) + 65536 (partials) + ints
#define RNN_SMEM (16384 + 65536 + 96)

// mlp smem layout (grp-major pB: 4*256*8 ull = 64 KB)
#define MLP_HT2  0
#define MLP_PB   16384
#define MLP_HLIN 81920
#define MLP_RED  98304
#define MLP_SMEM (98304 + 5120)

// setup kernel block ranges (all 256-thread blocks)
#define SETUP_TR_BLKS   128
#define SETUP_W2_BASE   128
#define SETUP_P_BASE    144
#define SETUP_SORT_BASE 272
#define SETUP_GRID      276

// Scratch (no allocations allowed -> __device__ globals)
__device__ float  g_P[V * H];                   // emb @ W_ih^T + b_ih + b_hh
__device__ float4 g_Wp[(H / 2) * (H / 2)];      // paired W_hh^T (1 MB)
__device__ float4 g_W1p[(H / 2) * (H / 2)];     // paired W1^T   (1 MB)
__device__ float  g_W2T[H * C];                 // W2^T [k][c]
__device__ float  g_last[B * H];                // h at t=len-1, original order
__device__ int    g_sidx[B];
__device__ int    g_slen[B];

// ---------------------------------------------------------------------------
// f32x2 helpers
// ---------------------------------------------------------------------------
typedef unsigned long long ull;
__device__ __forceinline__ ull pk2(float x, float y) {
    ull r; asm("mov.b64 %0, {%1, %2};" : "=l"(r) : "f"(x), "f"(y)); return r;
}
__device__ __forceinline__ void upk2(ull v, float& x, float& y) {
    asm("mov.b64 {%0, %1}, %2;" : "=f"(x), "=f"(y) : "l"(v));
}
__device__ __forceinline__ void fma2(ull& d, ull a, ull b) {
    asm("fma.rn.f32x2 %0, %1, %2, %3;" : "=l"(d) : "l"(a), "l"(b), "l"(d));
}
__device__ __forceinline__ void add2(ull& d, ull a, ull b) {
    asm("add.rn.f32x2 %0, %1, %2;" : "=l"(d) : "l"(a), "l"(b));
}

// ---------------------------------------------------------------------------
// Fused setup kernel (round-13 version, unchanged)
// ---------------------------------------------------------------------------
__global__ void __launch_bounds__(256) setup_kernel(
        const int*   __restrict__ lens,
        const float* __restrict__ emb,
        const float* __restrict__ W_ih,
        const float* __restrict__ b_ih,
        const float* __restrict__ b_hh,
        const float* __restrict__ W_hh,
        const float* __restrict__ W1,
        const float* __restrict__ W2) {
    const int bid = blockIdx.x;
    const int tid = threadIdx.x;

    if (bid < SETUP_TR_BLKS) {
        __shared__ float ts[64][65];            // padded
        const int  m  = bid >> 6;               // 0: W_hh, 1: W1
        const int  tb = bid & 63;
        const int  th = tb & 7;                 // h-tile
        const int  tk = tb >> 3;                // k-tile
        const float* src = m ? W1 : W_hh;

#pragma unroll
        for (int j = 0; j < 4; j++) {
            const int idx = tid + j * 256;
            const int row = idx >> 4;
            const int c4  = idx & 15;
            float4 v = __ldg(reinterpret_cast<const float4*>(
                                 src + (64 * th + row) * H + 64 * tk) + c4);
            ts[row][4 * c4 + 0] = v.x;
            ts[row][4 * c4 + 1] = v.y;
            ts[row][4 * c4 + 2] = v.z;
            ts[row][4 * c4 + 3] = v.w;
        }
        __syncthreads();

        float4* dst = m ? g_W1p : g_Wp;
#pragma unroll
        for (int j = 0; j < 4; j++) {
            const int idx  = tid + j * 256;
            const int kp_l = idx >> 5;
            const int hp_l = idx & 31;
            const int lh = 2 * hp_l, lk = 2 * kp_l;
            float4 v = make_float4(ts[lh][lk],     ts[lh + 1][lk],
                                   ts[lh][lk + 1], ts[lh + 1][lk + 1]);
            dst[(32 * tk + kp_l) * 256 + (32 * th + hp_l)] = v;
        }
    } else if (bid < SETUP_P_BASE) {
        const int q  = (bid - SETUP_W2_BASE) * 256 + tid;
        const int k  = q >> 3;
        const int c0 = (q & 7) * 4;
        float4 v;
        v.x = __ldg(W2 + (c0 + 0) * H + k);
        v.y = __ldg(W2 + (c0 + 1) * H + k);
        v.z = __ldg(W2 + (c0 + 2) * H + k);
        v.w = __ldg(W2 + (c0 + 3) * H + k);
        reinterpret_cast<float4*>(g_W2T)[q] = v;
    } else if (bid < SETUP_SORT_BASE) {
        __shared__ float es[E];
        const int v = bid - SETUP_P_BASE;
        es[tid] = emb[v * E + tid];
        __syncthreads();
        const float4* e4 = reinterpret_cast<const float4*>(es);
#pragma unroll
        for (int r = 0; r < 2; r++) {
            const int h = tid + r * 256;
            float acc = b_ih[h] + b_hh[h];
            const float4* w = reinterpret_cast<const float4*>(W_ih + h * E);
#pragma unroll 8
            for (int i = 0; i < E / 4; i++) {
                float4 a = e4[i], b = w[i];
                acc += a.x * b.x + a.y * b.y + a.z * b.z + a.w * b.w;
            }
            g_P[v * H + h] = acc;
        }
    } else {
        __shared__ int sl[B];
        for (int j = tid; j < B; j += 256) sl[j] = __ldg(lens + j);
        __syncthreads();
        const int i  = (bid - SETUP_SORT_BASE) * 256 + tid;
        const int my = sl[i];
        int rank = 0;
#pragma unroll 8
        for (int j = 0; j < B; j++) {
            int lj = sl[j];
            rank += (lj < my) || (lj == my && j < i);
        }
        g_sidx[rank] = i;
        g_slen[rank] = my;
    }
}

// ---------------------------------------------------------------------------
// Packed-batch inner compute (NB8 + mlp): 4 kp (8 k), weights in regs.
// ---------------------------------------------------------------------------
template <int NB>
__device__ __forceinline__ void comp4T(const ull* __restrict__ hT2, int k0,
                                       const ulonglong2 w[4],
                                       ull* __restrict__ a0, ull* __restrict__ a1) {
#pragma unroll
    for (int j = 0; j < 4; j++) {
#pragma unroll
        for (int kk = 0; kk < 2; kk++) {
            const int k = k0 + 2 * j + kk;
            float wl, wh;
            upk2(kk ? w[j].y : w[j].x, wl, wh);
            ull s0 = pk2(wl, wl), s1 = pk2(wh, wh);
            const ulonglong2* hk =
                reinterpret_cast<const ulonglong2*>(hT2 + (unsigned)k * (NB / 2));
#pragma unroll
            for (int p = 0; p < NB / 4; p++) {
                ulonglong2 hv = hk[p];
                fma2(a0[2 * p], hv.x, s0); fma2(a0[2 * p + 1], hv.y, s0);
                fma2(a1[2 * p], hv.x, s1); fma2(a1[2 * p + 1], hv.y, s1);
            }
        }
    }
}

// 64-kp GEMM pass: 8-kp chunks, double-buffered W prefetch
template <int NB>
__device__ __forceinline__ void gemm_g6(const ulonglong2* __restrict__ Wp,
                                        const ull* __restrict__ hT2, int kbase,
                                        ull* __restrict__ a0, ull* __restrict__ a1) {
    ulonglong2 wA[4], wB[4];
#pragma unroll
    for (int j = 0; j < 4; j++) wA[j] = __ldg(Wp + j * HPAIR);
#pragma unroll 1
    for (int c = 0; c < 64; c += 8) {
#pragma unroll
        for (int j = 0; j < 4; j++) wB[j] = __ldg(Wp + (c + 4 + j) * HPAIR);
        comp4T<NB>(hT2, kbase + 2 * c, wA, a0, a1);
        const int nc = (c + 8) & 63;        // wrap dummy on last iter
#pragma unroll
        for (int j = 0; j < 4; j++) wA[j] = __ldg(Wp + (nc + j) * HPAIR);
        comp4T<NB>(hT2, kbase + 2 * (c + 4), wB, a0, a1);
    }
}

// ---------------------------------------------------------------------------
// NB=8 RNN body: 4-way k-split; pB now GRP-MAJOR [grp][hp][8] (conflict-free).
//   write: pB + grp*2048 + hp*8      (warp: 2KB contiguous STS.128)
//   read:  pB + g*2048 + eh*4 + eq*2 (warp: 512B contiguous LDS.64)
// ---------------------------------------------------------------------------
__device__ __forceinline__ void rnn_body8(const int* __restrict__ x_in,
                                          int rowbase, char* smem) {
    constexpr int NB = 8;
    ull* hT2 = reinterpret_cast<ull*>(smem);                   // [512][4]
    ull* pB  = hT2 + 512 * 4;                                  // [4][256][8]
    int* ints = reinterpret_cast<int*>(pB + 4 * 256 * 8);
    int* orig = ints;
    int* slen = ints + NB;
    int* xi   = ints + 2 * NB;

    const int tid = threadIdx.x;
    const int grp = tid >> 8;
    const int hp  = tid & (HPAIR - 1);

    const int eh   = tid >> 1;
    const int eq   = tid & 1;

    if (tid < NB) {
        orig[tid] = g_sidx[rowbase + tid];
        slen[tid] = g_slen[rowbase + tid];
    }
    for (int i = tid; i < 512 * 4; i += THR) hT2[i] = 0ull;
    __syncthreads();

    int tmax = 0;
#pragma unroll
    for (int b = 0; b < NB; b++) tmax = max(tmax, slen[b]);

    const ulonglong2* Wp =
        reinterpret_cast<const ulonglong2*>(g_Wp) + (grp * 64) * HPAIR + hp;
    const int kbase = grp * 128;

    ull*       myPB = pB + grp * 2048 + hp * 8;
    const ull* ePB  = pB + eh * 4 + eq * 2;   // +g*2048 in the loop

    for (int t = 0; t < tmax; t++) {
        if (tid < NB) xi[tid] = x_in[orig[tid] * S + t];
        __syncthreads();

        float pf[4];
#pragma unroll
        for (int i = 0; i < 4; i++)
            pf[i] = __ldg(g_P + xi[eq * 4 + i] * H + eh);

        ull a0[4], a1[4];
#pragma unroll
        for (int p = 0; p < 4; p++) { a0[p] = 0ull; a1[p] = 0ull; }

        gemm_g6<8>(Wp, hT2, kbase, a0, a1);

        // grp-major partial write: 64B contiguous per thread
#pragma unroll
        for (int p = 0; p < 4; p += 2)
            *reinterpret_cast<ulonglong2*>(myPB + p) =
                make_ulonglong2(a0[p], a0[p + 1]);
#pragma unroll
        for (int p = 0; p < 4; p += 2)
            *reinterpret_cast<ulonglong2*>(myPB + 4 + p) =
                make_ulonglong2(a1[p], a1[p + 1]);
        __syncthreads();

        // epilogue: thread (eh, eq) reduces its 2 ull across 4 groups
        ull s[2];
#pragma unroll
        for (int q = 0; q < 2; q++) s[q] = ePB[q];
#pragma unroll
        for (int g = 1; g < 4; g++) {
#pragma unroll
            for (int q = 0; q < 2; q++) {
                ull v = ePB[g * 2048 + q];
                add2(s[q], s[q], v);
            }
        }
#pragma unroll
        for (int q = 0; q < 2; q++)
            add2(s[q], s[q], pk2(pf[2 * q], pf[2 * q + 1]));

        float v[4];
#pragma unroll
        for (int q = 0; q < 2; q++) {
            float x, y;
            upk2(s[q], x, y);
            v[2 * q]     = tanhf(x);
            v[2 * q + 1] = tanhf(y);
        }
#pragma unroll
        for (int q = 0; q < 2; q++)
            hT2[eh * 4 + eq * 2 + q] = pk2(v[2 * q], v[2 * q + 1]);

#pragma unroll
        for (int i = 0; i < 4; i++) {
            const int b = eq * 4 + i;
            if (t == slen[b] - 1) g_last[orig[b] * H + eh] = v[i];
        }
    }
}

// ---------------------------------------------------------------------------
// NB=4 RNN body: 8-way k-split; pB GRP-MAJOR [grp][hp][4] (conflict-free).
//   write: pB + grp*1024 + hp*4        (warp: 1KB contiguous STS.128)
//   read:  pB + g*1024 + ehp*4 + eb    (warp: 256B contiguous LDS.64)
// ---------------------------------------------------------------------------
__device__ __forceinline__ void rnn_body4(const int* __restrict__ x_in,
                                          int rowbase, char* smem) {
    ull* hd = reinterpret_cast<ull*>(smem);                    // [256][4] float2
    ull* pB = hd + 256 * 4;                                    // [8][256][4]
    int* ints = reinterpret_cast<int*>(pB + 8 * 256 * 4);
    int* orig = ints;
    int* slen = ints + 4;
    int* xi   = ints + 8;

    const int tid = threadIdx.x;
    const int grp = tid >> 7;              // 0..7
    const int u   = tid & 127;
    const int hp0 = u;
    const int hp1 = u + 128;

    // epilogue role: thread = (h-pair ehp, batch eb)
    const int ehp = tid >> 2;              // 0..255
    const int eb  = tid & 3;

    if (tid < 4) {
        orig[tid] = g_sidx[rowbase + tid];
        slen[tid] = g_slen[rowbase + tid];
    }
    for (int i = tid; i < 256 * 4; i += THR) hd[i] = 0ull;
    __syncthreads();

    int tmax = 0;
#pragma unroll
    for (int b = 0; b < 4; b++) tmax = max(tmax, slen[b]);

    const ulonglong2* Wb = reinterpret_cast<const ulonglong2*>(g_Wp);
    const int kb = grp * 32;               // kp base for this group

    ull*       wr0 = pB + grp * 1024 + hp0 * 4;
    ull*       wr1 = pB + grp * 1024 + hp1 * 4;
    const ull* rd  = pB + ehp * 4 + eb;    // +g*1024 in the loop

    for (int t = 0; t < tmax; t++) {
        if (tid < 4) xi[tid] = x_in[orig[tid] * S + t];
        __syncthreads();    // (1) xi ready; hd from previous epilogue visible

        float2 pf = __ldg(reinterpret_cast<const float2*>(g_P + xi[eb] * H) + ehp);

        ull a0[4], a1[4];
#pragma unroll
        for (int b = 0; b < 4; b++) { a0[b] = 0ull; a1[b] = 0ull; }

        // 32 kp, 2-kp unrolled, double-buffered W prefetch
        ulonglong2 wa0 = __ldg(Wb + (kb + 0) * HPAIR + hp0);
        ulonglong2 wa1 = __ldg(Wb + (kb + 0) * HPAIR + hp1);
        ulonglong2 wc0 = __ldg(Wb + (kb + 1) * HPAIR + hp0);
        ulonglong2 wc1 = __ldg(Wb + (kb + 1) * HPAIR + hp1);
#pragma unroll 4
        for (int c = 0; c < 32; c += 2) {
            const int n0 = (c + 2) & 31;
            const int n1 = (c + 3) & 31;
            ulonglong2 wb0 = __ldg(Wb + (kb + n0) * HPAIR + hp0);
            ulonglong2 wb1 = __ldg(Wb + (kb + n0) * HPAIR + hp1);
            {
                const float4* hk =
                    reinterpret_cast<const float4*>(hd + (unsigned)(kb + c) * 4);
                float4 qA = hk[0];   // b0:(ke,ko), b1:(ke,ko)
                float4 qB = hk[1];   // b2:(ke,ko), b3:(ke,ko)
                {   // k even
                    ull d0 = pk2(qA.x, qA.x), d1 = pk2(qA.z, qA.z);
                    ull d2 = pk2(qB.x, qB.x), d3 = pk2(qB.z, qB.z);
                    fma2(a0[0], wa0.x, d0); fma2(a0[1], wa0.x, d1);
                    fma2(a0[2], wa0.x, d2); fma2(a0[3], wa0.x, d3);
                    fma2(a1[0], wa1.x, d0); fma2(a1[1], wa1.x, d1);
                    fma2(a1[2], wa1.x, d2); fma2(a1[3], wa1.x, d3);
                }
                {   // k odd
                    ull d0 = pk2(qA.y, qA.y), d1 = pk2(qA.w, qA.w);
                    ull d2 = pk2(qB.y, qB.y), d3 = pk2(qB.w, qB.w);
                    fma2(a0[0], wa0.y, d0); fma2(a0[1], wa0.y, d1);
                    fma2(a0[2], wa0.y, d2); fma2(a0[3], wa0.y, d3);
                    fma2(a1[0], wa1.y, d0); fma2(a1[1], wa1.y, d1);
                    fma2(a1[2], wa1.y, d2); fma2(a1[3], wa1.y, d3);
                }
            }
            ulonglong2 wd0 = __ldg(Wb + (kb + n1) * HPAIR + hp0);
            ulonglong2 wd1 = __ldg(Wb + (kb + n1) * HPAIR + hp1);
            {
                const float4* hk =
                    reinterpret_cast<const float4*>(hd + (unsigned)(kb + c + 1) * 4);
                float4 qA = hk[0];
                float4 qB = hk[1];
                {   // k even
                    ull d0 = pk2(qA.x, qA.x), d1 = pk2(qA.z, qA.z);
                    ull d2 = pk2(qB.x, qB.x), d3 = pk2(qB.z, qB.z);
                    fma2(a0[0], wc0.x, d0); fma2(a0[1], wc0.x, d1);
                    fma2(a0[2], wc0.x, d2); fma2(a0[3], wc0.x, d3);
                    fma2(a1[0], wc1.x, d0); fma2(a1[1], wc1.x, d1);
                    fma2(a1[2], wc1.x, d2); fma2(a1[3], wc1.x, d3);
                }
                {   // k odd
                    ull d0 = pk2(qA.y, qA.y), d1 = pk2(qA.w, qA.w);
                    ull d2 = pk2(qB.y, qB.y), d3 = pk2(qB.w, qB.w);
                    fma2(a0[0], wc0.y, d0); fma2(a0[1], wc0.y, d1);
                    fma2(a0[2], wc0.y, d2); fma2(a0[3], wc0.y, d3);
                    fma2(a1[0], wc1.y, d0); fma2(a1[1], wc1.y, d1);
                    fma2(a1[2], wc1.y, d2); fma2(a1[3], wc1.y, d3);
                }
            }
            wa0 = wb0; wa1 = wb1; wc0 = wd0; wc1 = wd1;
        }

        // grp-major partial write: 32B contiguous per thread, warp = 1KB run
        *reinterpret_cast<ulonglong2*>(wr0)     = make_ulonglong2(a0[0], a0[1]);
        *reinterpret_cast<ulonglong2*>(wr0 + 2) = make_ulonglong2(a0[2], a0[3]);
        *reinterpret_cast<ulonglong2*>(wr1)     = make_ulonglong2(a1[0], a1[1]);
        *reinterpret_cast<ulonglong2*>(wr1 + 2) = make_ulonglong2(a1[2], a1[3]);
        __syncthreads();    // (2) partials visible; all hd reads complete

        // distributed epilogue: (h-pair ehp, batch eb)
        ull s = rd[0];
#pragma unroll
        for (int g = 1; g < 8; g++) {
            ull v = rd[g * 1024];
            add2(s, s, v);
        }
        add2(s, s, pk2(pf.x, pf.y));

        float x0, x1;
        upk2(s, x0, x1);
        const float v0 = tanhf(x0);
        const float v1 = tanhf(x1);

        // non-duplicated state write: one STS.64 per thread
        hd[ehp * 4 + eb] = pk2(v0, v1);

        if (t == slen[eb] - 1)
            *reinterpret_cast<float2*>(g_last + orig[eb] * H + 2 * ehp) =
                make_float2(v0, v1);
    }
}

// ---------------------------------------------------------------------------
// Kernel: bucketed persistent RNN (same schedule as rounds 7-13).
// ---------------------------------------------------------------------------
__global__ void __launch_bounds__(THR, 1) rnn_kernel(const int* __restrict__ x_in) {
    extern __shared__ char smem[];
    const int bid = blockIdx.x;
    if (bid < N_CTA4) {
        rnn_body4(x_in, 608 + 4 * bid, smem);
    } else {
        rnn_body8(x_in, 600 - 8 * (bid - N_CTA4), smem);
    }
}

// ---------------------------------------------------------------------------
// Kernel: MLP head — one rnn-style NB=8 step (relu) + k-split logits.
// pB grp-major like rnn_body8.
// ---------------------------------------------------------------------------
__global__ void __launch_bounds__(THR, 1) mlp_kernel(const float* __restrict__ b1,
                                                     const float* __restrict__ b2,
                                                     float* __restrict__ out) {
    extern __shared__ char smem[];
    ull*   hT2  = reinterpret_cast<ull*>(smem + MLP_HT2);    // [512][4]
    ull*   pB   = reinterpret_cast<ull*>(smem + MLP_PB);     // [4][256][8]
    float* hlin = reinterpret_cast<float*>(smem + MLP_HLIN); // [8][512]
    float* red  = reinterpret_cast<float*>(smem + MLP_RED);  // [256][5]

    const int tid  = threadIdx.x;
    const int grp  = tid >> 8;
    const int hp   = tid & (HPAIR - 1);
    const int base = blockIdx.x * BT;

    const int eh   = tid >> 1;
    const int eq   = tid & 1;

    hT2[eh * 4 + 2 * eq + 0] = pk2(g_last[(base + 4 * eq + 0) * H + eh],
                                   g_last[(base + 4 * eq + 1) * H + eh]);
    hT2[eh * 4 + 2 * eq + 1] = pk2(g_last[(base + 4 * eq + 2) * H + eh],
                                   g_last[(base + 4 * eq + 3) * H + eh]);
    __syncthreads();

    const ulonglong2* Wp =
        reinterpret_cast<const ulonglong2*>(g_W1p) + (grp * 64) * HPAIR + hp;

    ull a0[4], a1[4];
#pragma unroll
    for (int p = 0; p < 4; p++) { a0[p] = 0ull; a1[p] = 0ull; }

    gemm_g6<8>(Wp, hT2, grp * 128, a0, a1);

    ull* myPB = pB + grp * 2048 + hp * 8;
#pragma unroll
    for (int p = 0; p < 4; p += 2)
        *reinterpret_cast<ulonglong2*>(myPB + p) = make_ulonglong2(a0[p], a0[p + 1]);
#pragma unroll
    for (int p = 0; p < 4; p += 2)
        *reinterpret_cast<ulonglong2*>(myPB + 4 + p) = make_ulonglong2(a1[p], a1[p + 1]);
    __syncthreads();

    {
        const ull* ePB = pB + eh * 4 + eq * 2;
        ull s[2];
#pragma unroll
        for (int q = 0; q < 2; q++) s[q] = ePB[q];
#pragma unroll
        for (int g = 1; g < 4; g++) {
#pragma unroll
            for (int q = 0; q < 2; q++) {
                ull v = ePB[g * 2048 + q];
                add2(s[q], s[q], v);
            }
        }
        const float bv = __ldg(b1 + eh);
#pragma unroll
        for (int q = 0; q < 2; q++) {
            float x, y;
            upk2(s[q], x, y);
            hlin[(eq * 4 + 2 * q + 0) * H + eh] = fmaxf(x + bv, 0.f);
            hlin[(eq * 4 + 2 * q + 1) * H + eh] = fmaxf(y + bv, 0.f);
        }
    }
    __syncthreads();

    {
        const int kq = tid >> 8;
        const int r  = tid & 255;
        const int b  = r >> 5;
        const int c  = r & 31;
        float acc = 0.f;
        const float* hb = hlin + b * H + kq * 128;
        const float* w2 = g_W2T + (kq * 128) * C + c;
#pragma unroll 8
        for (int k = 0; k < 128; k++) acc += hb[k] * __ldg(w2 + k * C);
        red[r * 5 + kq] = acc;
    }
    __syncthreads();

    if (tid < 256) {
        const int b = tid >> 5, c = tid & 31;
        float acc = __ldg(b2 + c) + red[tid * 5 + 0] + red[tid * 5 + 1]
                  + red[tid * 5 + 2] + red[tid * 5 + 3];
        out[(base + b) * C + c] = acc;
    }
}

// ---------------------------------------------------------------------------
extern "C" void kernel_launch(void* const* d_in, const int* in_sizes, int n_in,
                              void* d_out, int out_size) {
    const int*   x_in   = (const int*)  d_in[0];
    const int*   x_lens = (const int*)  d_in[1];
    const float* emb    = (const float*)d_in[2];
    const float* W_ih   = (const float*)d_in[3];
    const float* b_ih   = (const float*)d_in[4];
    const float* W_hh   = (const float*)d_in[5];
    const float* b_hh   = (const float*)d_in[6];
    const float* W1w    = (const float*)d_in[7];
    const float* b1     = (const float*)d_in[8];
    const float* W2w    = (const float*)d_in[9];
    const float* b2     = (const float*)d_in[10];
    float* out = (float*)d_out;

    cudaFuncSetAttribute(rnn_kernel,
                         cudaFuncAttributeMaxDynamicSharedMemorySize, RNN_SMEM);
    cudaFuncSetAttribute(mlp_kernel,
                         cudaFuncAttributeMaxDynamicSharedMemorySize, MLP_SMEM);

    setup_kernel<<<SETUP_GRID, 256>>>(x_lens, emb, W_ih, b_ih, b_hh,
                                      W_hh, W1w, W2w);
    rnn_kernel<<<RNN_GRID, THR, RNN_SMEM>>>(x_in);
    mlp_kernel<<<B / BT, THR, MLP_SMEM>>>(b1, b2, out);
}

// round 15
// speedup vs baseline: 1.0334x; 1.0334x over previous
#include <cuda_runtime.h>
#include <math.h>

// Problem dims (fixed by the dataset)
#define B 1024
#define S 64
#define E 256
#define H 512
#define V 128
#define C 32

#define BT    8
#define HPAIR 256          // h-pairs
#define THR   1024

// buckets: NB4 CTAs (longest rows, 608..1023), NB8 CTAs (rows 0..607 desc)
#define N_CTA4  104
#define N_CTA8  76
#define RNN_GRID (N_CTA4 + N_CTA8)   // 180

// dynamic smem (worst case = NB8 path): 16384 (state) + 69632 (partials) + ints
#define RNN_SMEM (16384 + 69632 + 96)

// mlp smem layout (R13 padded pB)
#define MLP_HT2  0
#define MLP_PB   16384
#define MLP_HLIN 86016
#define MLP_RED  102400
#define MLP_SMEM (102400 + 5120)

// setup kernel block ranges (all 256-thread blocks)
#define SETUP_TR_BLKS   128
#define SETUP_W2_BASE   128
#define SETUP_P_BASE    144
#define SETUP_SORT_BASE 272
#define SETUP_GRID      276

// Scratch (no allocations allowed -> __device__ globals)
// W tables padded by 8 kp-rows so prefetch dummy loads past kp=255 stay
// in-bounds (values never consumed — only the fault matters).
__device__ float  g_P[V * H];                       // emb @ W_ih^T + b_ih + b_hh
__device__ float4 g_Wp[(H / 2) * (H / 2) + 8 * HPAIR];   // paired W_hh^T + pad
__device__ float4 g_W1p[(H / 2) * (H / 2) + 8 * HPAIR];  // paired W1^T   + pad
__device__ float  g_W2T[H * C];                     // W2^T [k][c]
__device__ float  g_last[B * H];                    // h at t=len-1, original order
__device__ int    g_sidx[B];
__device__ int    g_slen[B];

// ---------------------------------------------------------------------------
// f32x2 helpers
// ---------------------------------------------------------------------------
typedef unsigned long long ull;
__device__ __forceinline__ ull pk2(float x, float y) {
    ull r; asm("mov.b64 %0, {%1, %2};" : "=l"(r) : "f"(x), "f"(y)); return r;
}
__device__ __forceinline__ void upk2(ull v, float& x, float& y) {
    asm("mov.b64 {%0, %1}, %2;" : "=f"(x), "=f"(y) : "l"(v));
}
__device__ __forceinline__ void fma2(ull& d, ull a, ull b) {
    asm("fma.rn.f32x2 %0, %1, %2, %3;" : "=l"(d) : "l"(a), "l"(b), "l"(d));
}
__device__ __forceinline__ void add2(ull& d, ull a, ull b) {
    asm("add.rn.f32x2 %0, %1, %2;" : "=l"(d) : "l"(a), "l"(b));
}

// ---------------------------------------------------------------------------
// Fused setup kernel (R13 version, unchanged)
// ---------------------------------------------------------------------------
__global__ void __launch_bounds__(256) setup_kernel(
        const int*   __restrict__ lens,
        const float* __restrict__ emb,
        const float* __restrict__ W_ih,
        const float* __restrict__ b_ih,
        const float* __restrict__ b_hh,
        const float* __restrict__ W_hh,
        const float* __restrict__ W1,
        const float* __restrict__ W2) {
    const int bid = blockIdx.x;
    const int tid = threadIdx.x;

    if (bid < SETUP_TR_BLKS) {
        __shared__ float ts[64][65];            // padded
        const int  m  = bid >> 6;               // 0: W_hh, 1: W1
        const int  tb = bid & 63;
        const int  th = tb & 7;                 // h-tile
        const int  tk = tb >> 3;                // k-tile
        const float* src = m ? W1 : W_hh;

#pragma unroll
        for (int j = 0; j < 4; j++) {
            const int idx = tid + j * 256;
            const int row = idx >> 4;
            const int c4  = idx & 15;
            float4 v = __ldg(reinterpret_cast<const float4*>(
                                 src + (64 * th + row) * H + 64 * tk) + c4);
            ts[row][4 * c4 + 0] = v.x;
            ts[row][4 * c4 + 1] = v.y;
            ts[row][4 * c4 + 2] = v.z;
            ts[row][4 * c4 + 3] = v.w;
        }
        __syncthreads();

        float4* dst = m ? g_W1p : g_Wp;
#pragma unroll
        for (int j = 0; j < 4; j++) {
            const int idx  = tid + j * 256;
            const int kp_l = idx >> 5;
            const int hp_l = idx & 31;
            const int lh = 2 * hp_l, lk = 2 * kp_l;
            float4 v = make_float4(ts[lh][lk],     ts[lh + 1][lk],
                                   ts[lh][lk + 1], ts[lh + 1][lk + 1]);
            dst[(32 * tk + kp_l) * 256 + (32 * th + hp_l)] = v;
        }
    } else if (bid < SETUP_P_BASE) {
        const int q  = (bid - SETUP_W2_BASE) * 256 + tid;
        const int k  = q >> 3;
        const int c0 = (q & 7) * 4;
        float4 v;
        v.x = __ldg(W2 + (c0 + 0) * H + k);
        v.y = __ldg(W2 + (c0 + 1) * H + k);
        v.z = __ldg(W2 + (c0 + 2) * H + k);
        v.w = __ldg(W2 + (c0 + 3) * H + k);
        reinterpret_cast<float4*>(g_W2T)[q] = v;
    } else if (bid < SETUP_SORT_BASE) {
        __shared__ float es[E];
        const int v = bid - SETUP_P_BASE;
        es[tid] = emb[v * E + tid];
        __syncthreads();
        const float4* e4 = reinterpret_cast<const float4*>(es);
#pragma unroll
        for (int r = 0; r < 2; r++) {
            const int h = tid + r * 256;
            float acc = b_ih[h] + b_hh[h];
            const float4* w = reinterpret_cast<const float4*>(W_ih + h * E);
#pragma unroll 8
            for (int i = 0; i < E / 4; i++) {
                float4 a = e4[i], b = w[i];
                acc += a.x * b.x + a.y * b.y + a.z * b.z + a.w * b.w;
            }
            g_P[v * H + h] = acc;
        }
    } else {
        __shared__ int sl[B];
        for (int j = tid; j < B; j += 256) sl[j] = __ldg(lens + j);
        __syncthreads();
        const int i  = (bid - SETUP_SORT_BASE) * 256 + tid;
        const int my = sl[i];
        int rank = 0;
#pragma unroll 8
        for (int j = 0; j < B; j++) {
            int lj = sl[j];
            rank += (lj < my) || (lj == my && j < i);
        }
        g_sidx[rank] = i;
        g_slen[rank] = my;
    }
}

// ---------------------------------------------------------------------------
// Packed-batch inner compute (NB8 + mlp): 4 kp (8 k), weights in regs.
// ---------------------------------------------------------------------------
template <int NB>
__device__ __forceinline__ void comp4T(const ull* __restrict__ hT2, int k0,
                                       const ulonglong2 w[4],
                                       ull* __restrict__ a0, ull* __restrict__ a1) {
#pragma unroll
    for (int j = 0; j < 4; j++) {
#pragma unroll
        for (int kk = 0; kk < 2; kk++) {
            const int k = k0 + 2 * j + kk;
            float wl, wh;
            upk2(kk ? w[j].y : w[j].x, wl, wh);
            ull s0 = pk2(wl, wl), s1 = pk2(wh, wh);
            const ulonglong2* hk =
                reinterpret_cast<const ulonglong2*>(hT2 + (unsigned)k * (NB / 2));
#pragma unroll
            for (int p = 0; p < NB / 4; p++) {
                ulonglong2 hv = hk[p];
                fma2(a0[2 * p], hv.x, s0); fma2(a0[2 * p + 1], hv.y, s0);
                fma2(a1[2 * p], hv.x, s1); fma2(a1[2 * p + 1], hv.y, s1);
            }
        }
    }
}

// 64-kp GEMM pass: 8-kp chunks, double-buffered W prefetch.
// No wrap masks: tail prefetch runs into the padded rows (dummy loads).
template <int NB>
__device__ __forceinline__ void gemm_g6(const ulonglong2* __restrict__ Wp,
                                        const ull* __restrict__ hT2, int kbase,
                                        ull* __restrict__ a0, ull* __restrict__ a1) {
    ulonglong2 wA[4], wB[4];
#pragma unroll
    for (int j = 0; j < 4; j++) wA[j] = __ldg(Wp + j * HPAIR);
#pragma unroll 1
    for (int c = 0; c < 64; c += 8) {
#pragma unroll
        for (int j = 0; j < 4; j++) wB[j] = __ldg(Wp + (c + 4 + j) * HPAIR);
        comp4T<NB>(hT2, kbase + 2 * c, wA, a0, a1);
#pragma unroll
        for (int j = 0; j < 4; j++) wA[j] = __ldg(Wp + (c + 8 + j) * HPAIR);
        comp4T<NB>(hT2, kbase + 2 * (c + 4), wB, a0, a1);
    }
}

// ---------------------------------------------------------------------------
// NB=8 RNN body (R13): 4-way k-split, packed-batch state, pB [hp][34].
// ---------------------------------------------------------------------------
__device__ __forceinline__ void rnn_body8(const int* __restrict__ x_in,
                                          int rowbase, char* smem) {
    constexpr int NB = 8;
    constexpr int PBS = 34;
    ull* hT2 = reinterpret_cast<ull*>(smem);                   // [512][4]
    ull* pB  = hT2 + 512 * 4;                                  // [256][34]
    int* ints = reinterpret_cast<int*>(pB + 256 * PBS);
    int* orig = ints;
    int* slen = ints + NB;
    int* xi   = ints + 2 * NB;

    const int tid = threadIdx.x;
    const int grp = tid >> 8;
    const int hp  = tid & (HPAIR - 1);

    const int eh   = tid >> 1;
    const int eq   = tid & 1;
    const int ehp  = eh >> 1;
    const int epar = eh & 1;

    if (tid < NB) {
        orig[tid] = g_sidx[rowbase + tid];
        slen[tid] = g_slen[rowbase + tid];
    }
    for (int i = tid; i < 512 * 4; i += THR) hT2[i] = 0ull;
    __syncthreads();

    int tmax = 0;
#pragma unroll
    for (int b = 0; b < NB; b++) tmax = max(tmax, slen[b]);

    const ulonglong2* Wp =
        reinterpret_cast<const ulonglong2*>(g_Wp) + (grp * 64) * HPAIR + hp;
    const int kbase = grp * 128;

    ull*       myPB = pB + hp * PBS + grp * NB;
    const ull* ePB  = pB + ehp * PBS + epar * 4 + eq * 2;

    for (int t = 0; t < tmax; t++) {
        if (tid < NB) xi[tid] = x_in[orig[tid] * S + t];
        __syncthreads();

        float pf[4];
#pragma unroll
        for (int i = 0; i < 4; i++)
            pf[i] = __ldg(g_P + xi[eq * 4 + i] * H + eh);

        ull a0[4], a1[4];
#pragma unroll
        for (int p = 0; p < 4; p++) { a0[p] = 0ull; a1[p] = 0ull; }

        gemm_g6<8>(Wp, hT2, kbase, a0, a1);

#pragma unroll
        for (int p = 0; p < 4; p += 2)
            *reinterpret_cast<ulonglong2*>(myPB + p) =
                make_ulonglong2(a0[p], a0[p + 1]);
#pragma unroll
        for (int p = 0; p < 4; p += 2)
            *reinterpret_cast<ulonglong2*>(myPB + 4 + p) =
                make_ulonglong2(a1[p], a1[p + 1]);
        __syncthreads();

        ull s[2];
#pragma unroll
        for (int q = 0; q < 2; q++) s[q] = ePB[q];
#pragma unroll
        for (int g = 1; g < 4; g++) {
#pragma unroll
            for (int q = 0; q < 2; q++) {
                ull v = ePB[g * NB + q];
                add2(s[q], s[q], v);
            }
        }
#pragma unroll
        for (int q = 0; q < 2; q++)
            add2(s[q], s[q], pk2(pf[2 * q], pf[2 * q + 1]));

        float v[4];
#pragma unroll
        for (int q = 0; q < 2; q++) {
            float x, y;
            upk2(s[q], x, y);
            v[2 * q]     = tanhf(x);
            v[2 * q + 1] = tanhf(y);
        }
#pragma unroll
        for (int q = 0; q < 2; q++)
            hT2[eh * 4 + eq * 2 + q] = pk2(v[2 * q], v[2 * q + 1]);

#pragma unroll
        for (int i = 0; i < 4; i++) {
            const int b = eq * 4 + i;
            if (t == slen[b] - 1) g_last[orig[b] * H + eh] = v[i];
        }
    }
}

// ---------------------------------------------------------------------------
// NB=4 RNN body (R13): non-duplicated state, pB [hp][34]; wrap masks removed
// (padded W table absorbs the dummy tail prefetch).
// ---------------------------------------------------------------------------
__device__ __forceinline__ void rnn_body4(const int* __restrict__ x_in,
                                          int rowbase, char* smem) {
    ull* hd = reinterpret_cast<ull*>(smem);                    // [256][4] float2
    ull* pB = hd + 256 * 4;                                    // [256][34]
    int* ints = reinterpret_cast<int*>(pB + 256 * 34);
    int* orig = ints;
    int* slen = ints + 4;
    int* xi   = ints + 8;

    const int tid = threadIdx.x;
    const int grp = tid >> 7;              // 0..7
    const int u   = tid & 127;
    const int hp0 = u;
    const int hp1 = u + 128;

    // epilogue role: thread = (h-pair ehp, batch eb)
    const int ehp = tid >> 2;              // 0..255
    const int eb  = tid & 3;

    if (tid < 4) {
        orig[tid] = g_sidx[rowbase + tid];
        slen[tid] = g_slen[rowbase + tid];
    }
    for (int i = tid; i < 256 * 4; i += THR) hd[i] = 0ull;
    __syncthreads();

    int tmax = 0;
#pragma unroll
    for (int b = 0; b < 4; b++) tmax = max(tmax, slen[b]);

    const ulonglong2* Wb = reinterpret_cast<const ulonglong2*>(g_Wp);
    const int kb = grp * 32;               // kp base for this group

    ull*       wr0 = pB + hp0 * 34 + grp * 4;
    ull*       wr1 = pB + hp1 * 34 + grp * 4;
    const ull* rd  = pB + ehp * 34 + eb;

    for (int t = 0; t < tmax; t++) {
        if (tid < 4) xi[tid] = x_in[orig[tid] * S + t];
        __syncthreads();    // (1) xi ready; hd from previous epilogue visible

        float2 pf = __ldg(reinterpret_cast<const float2*>(g_P + xi[eb] * H) + ehp);

        ull a0[4], a1[4];
#pragma unroll
        for (int b = 0; b < 4; b++) { a0[b] = 0ull; a1[b] = 0ull; }

        // 32 kp, 2-kp unrolled, double-buffered W prefetch (no wrap masks)
        ulonglong2 wa0 = __ldg(Wb + (kb + 0) * HPAIR + hp0);
        ulonglong2 wa1 = __ldg(Wb + (kb + 0) * HPAIR + hp1);
        ulonglong2 wc0 = __ldg(Wb + (kb + 1) * HPAIR + hp0);
        ulonglong2 wc1 = __ldg(Wb + (kb + 1) * HPAIR + hp1);
#pragma unroll 4
        for (int c = 0; c < 32; c += 2) {
            ulonglong2 wb0 = __ldg(Wb + (kb + c + 2) * HPAIR + hp0);
            ulonglong2 wb1 = __ldg(Wb + (kb + c + 2) * HPAIR + hp1);
            {
                const float4* hk =
                    reinterpret_cast<const float4*>(hd + (unsigned)(kb + c) * 4);
                float4 qA = hk[0];   // b0:(ke,ko), b1:(ke,ko)
                float4 qB = hk[1];   // b2:(ke,ko), b3:(ke,ko)
                {   // k even
                    ull d0 = pk2(qA.x, qA.x), d1 = pk2(qA.z, qA.z);
                    ull d2 = pk2(qB.x, qB.x), d3 = pk2(qB.z, qB.z);
                    fma2(a0[0], wa0.x, d0); fma2(a0[1], wa0.x, d1);
                    fma2(a0[2], wa0.x, d2); fma2(a0[3], wa0.x, d3);
                    fma2(a1[0], wa1.x, d0); fma2(a1[1], wa1.x, d1);
                    fma2(a1[2], wa1.x, d2); fma2(a1[3], wa1.x, d3);
                }
                {   // k odd
                    ull d0 = pk2(qA.y, qA.y), d1 = pk2(qA.w, qA.w);
                    ull d2 = pk2(qB.y, qB.y), d3 = pk2(qB.w, qB.w);
                    fma2(a0[0], wa0.y, d0); fma2(a0[1], wa0.y, d1);
                    fma2(a0[2], wa0.y, d2); fma2(a0[3], wa0.y, d3);
                    fma2(a1[0], wa1.y, d0); fma2(a1[1], wa1.y, d1);
                    fma2(a1[2], wa1.y, d2); fma2(a1[3], wa1.y, d3);
                }
            }
            ulonglong2 wd0 = __ldg(Wb + (kb + c + 3) * HPAIR + hp0);
            ulonglong2 wd1 = __ldg(Wb + (kb + c + 3) * HPAIR + hp1);
            {
                const float4* hk =
                    reinterpret_cast<const float4*>(hd + (unsigned)(kb + c + 1) * 4);
                float4 qA = hk[0];
                float4 qB = hk[1];
                {   // k even
                    ull d0 = pk2(qA.x, qA.x), d1 = pk2(qA.z, qA.z);
                    ull d2 = pk2(qB.x, qB.x), d3 = pk2(qB.z, qB.z);
                    fma2(a0[0], wc0.x, d0); fma2(a0[1], wc0.x, d1);
                    fma2(a0[2], wc0.x, d2); fma2(a0[3], wc0.x, d3);
                    fma2(a1[0], wc1.x, d0); fma2(a1[1], wc1.x, d1);
                    fma2(a1[2], wc1.x, d2); fma2(a1[3], wc1.x, d3);
                }
                {   // k odd
                    ull d0 = pk2(qA.y, qA.y), d1 = pk2(qA.w, qA.w);
                    ull d2 = pk2(qB.y, qB.y), d3 = pk2(qB.w, qB.w);
                    fma2(a0[0], wc0.y, d0); fma2(a0[1], wc0.y, d1);
                    fma2(a0[2], wc0.y, d2); fma2(a0[3], wc0.y, d3);
                    fma2(a1[0], wc1.y, d0); fma2(a1[1], wc1.y, d1);
                    fma2(a1[2], wc1.y, d2); fma2(a1[3], wc1.y, d3);
                }
            }
            wa0 = wb0; wa1 = wb1; wc0 = wd0; wc1 = wd1;
        }

        // write partials: pB[hp][grp][b]
        *reinterpret_cast<ulonglong2*>(wr0)     = make_ulonglong2(a0[0], a0[1]);
        *reinterpret_cast<ulonglong2*>(wr0 + 2) = make_ulonglong2(a0[2], a0[3]);
        *reinterpret_cast<ulonglong2*>(wr1)     = make_ulonglong2(a1[0], a1[1]);
        *reinterpret_cast<ulonglong2*>(wr1 + 2) = make_ulonglong2(a1[2], a1[3]);
        __syncthreads();    // (2) partials visible; all hd reads complete

        // distributed epilogue: (h-pair ehp, batch eb)
        ull s = rd[0];
#pragma unroll
        for (int g = 1; g < 8; g++) {
            ull v = rd[g * 4];
            add2(s, s, v);
        }
        add2(s, s, pk2(pf.x, pf.y));

        float x0, x1;
        upk2(s, x0, x1);
        const float v0 = tanhf(x0);
        const float v1 = tanhf(x1);

        // non-duplicated state write: one STS.64 per thread
        hd[ehp * 4 + eb] = pk2(v0, v1);

        if (t == slen[eb] - 1)
            *reinterpret_cast<float2*>(g_last + orig[eb] * H + 2 * ehp) =
                make_float2(v0, v1);
    }
}

// ---------------------------------------------------------------------------
// Kernel: bucketed persistent RNN (same schedule as rounds 7-13).
// ---------------------------------------------------------------------------
__global__ void __launch_bounds__(THR, 1) rnn_kernel(const int* __restrict__ x_in) {
    extern __shared__ char smem[];
    const int bid = blockIdx.x;
    if (bid < N_CTA4) {
        rnn_body4(x_in, 608 + 4 * bid, smem);
    } else {
        rnn_body8(x_in, 600 - 8 * (bid - N_CTA4), smem);
    }
}

// ---------------------------------------------------------------------------
// Kernel: MLP head (R13) — one rnn-style NB=8 step (relu) + k-split logits.
// ---------------------------------------------------------------------------
__global__ void __launch_bounds__(THR, 1) mlp_kernel(const float* __restrict__ b1,
                                                     const float* __restrict__ b2,
                                                     float* __restrict__ out) {
    extern __shared__ char smem[];
    ull*   hT2  = reinterpret_cast<ull*>(smem + MLP_HT2);    // [512][4]
    ull*   pB   = reinterpret_cast<ull*>(smem + MLP_PB);     // [256][34]
    float* hlin = reinterpret_cast<float*>(smem + MLP_HLIN); // [8][512]
    float* red  = reinterpret_cast<float*>(smem + MLP_RED);  // [256][5]

    const int tid  = threadIdx.x;
    const int grp  = tid >> 8;
    const int hp   = tid & (HPAIR - 1);
    const int base = blockIdx.x * BT;

    const int eh   = tid >> 1;
    const int eq   = tid & 1;
    const int ehp  = eh >> 1;
    const int epar = eh & 1;

    hT2[eh * 4 + 2 * eq + 0] = pk2(g_last[(base + 4 * eq + 0) * H + eh],
                                   g_last[(base + 4 * eq + 1) * H + eh]);
    hT2[eh * 4 + 2 * eq + 1] = pk2(g_last[(base + 4 * eq + 2) * H + eh],
                                   g_last[(base + 4 * eq + 3) * H + eh]);
    __syncthreads();

    const ulonglong2* Wp =
        reinterpret_cast<const ulonglong2*>(g_W1p) + (grp * 64) * HPAIR + hp;

    ull a0[4], a1[4];
#pragma unroll
    for (int p = 0; p < 4; p++) { a0[p] = 0ull; a1[p] = 0ull; }

    gemm_g6<8>(Wp, hT2, grp * 128, a0, a1);

    ull* myPB = pB + hp * 34 + grp * 8;
#pragma unroll
    for (int p = 0; p < 4; p += 2)
        *reinterpret_cast<ulonglong2*>(myPB + p) = make_ulonglong2(a0[p], a0[p + 1]);
#pragma unroll
    for (int p = 0; p < 4; p += 2)
        *reinterpret_cast<ulonglong2*>(myPB + 4 + p) = make_ulonglong2(a1[p], a1[p + 1]);
    __syncthreads();

    {
        const ull* ePB = pB + ehp * 34 + epar * 4 + eq * 2;
        ull s[2];
#pragma unroll
        for (int q = 0; q < 2; q++) s[q] = ePB[q];
#pragma unroll
        for (int g = 1; g < 4; g++) {
#pragma unroll
            for (int q = 0; q < 2; q++) {
                ull v = ePB[g * 8 + q];
                add2(s[q], s[q], v);
            }
        }
        const float bv = __ldg(b1 + eh);
#pragma unroll
        for (int q = 0; q < 2; q++) {
            float x, y;
            upk2(s[q], x, y);
            hlin[(eq * 4 + 2 * q + 0) * H + eh] = fmaxf(x + bv, 0.f);
            hlin[(eq * 4 + 2 * q + 1) * H + eh] = fmaxf(y + bv, 0.f);
        }
    }
    __syncthreads();

    {
        const int kq = tid >> 8;
        const int r  = tid & 255;
        const int b  = r >> 5;
        const int c  = r & 31;
        float acc = 0.f;
        const float* hb = hlin + b * H + kq * 128;
        const float* w2 = g_W2T + (kq * 128) * C + c;
#pragma unroll 8
        for (int k = 0; k < 128; k++) acc += hb[k] * __ldg(w2 + k * C);
        red[r * 5 + kq] = acc;
    }
    __syncthreads();

    if (tid < 256) {
        const int b = tid >> 5, c = tid & 31;
        float acc = __ldg(b2 + c) + red[tid * 5 + 0] + red[tid * 5 + 1]
                  + red[tid * 5 + 2] + red[tid * 5 + 3];
        out[(base + b) * C + c] = acc;
    }
}

// ---------------------------------------------------------------------------
extern "C" void kernel_launch(void* const* d_in, const int* in_sizes, int n_in,
                              void* d_out, int out_size) {
    const int*   x_in   = (const int*)  d_in[0];
    const int*   x_lens = (const int*)  d_in[1];
    const float* emb    = (const float*)d_in[2];
    const float* W_ih   = (const float*)d_in[3];
    const float* b_ih   = (const float*)d_in[4];
    const float* W_hh   = (const float*)d_in[5];
    const float* b_hh   = (const float*)d_in[6];
    const float* W1w    = (const float*)d_in[7];
    const float* b1     = (const float*)d_in[8];
    const float* W2w    = (const float*)d_in[9];
    const float* b2     = (const float*)d_in[10];
    float* out = (float*)d_out;

    cudaFuncSetAttribute(rnn_kernel,
                         cudaFuncAttributeMaxDynamicSharedMemorySize, RNN_SMEM);
    cudaFuncSetAttribute(mlp_kernel,
                         cudaFuncAttributeMaxDynamicSharedMemorySize, MLP_SMEM);

    setup_kernel<<<SETUP_GRID, 256>>>(x_lens, emb, W_ih, b_ih, b_hh,
                                      W_hh, W1w, W2w);
    rnn_kernel<<<RNN_GRID, THR, RNN_SMEM>>>(x_in);
    mlp_kernel<<<B / BT, THR, MLP_SMEM>>>(b1, b2, out);
}